// round 8
// baseline (speedup 1.0000x reference)
#include <cuda_runtime.h>
#include <cuda_bf16.h>
#include <math.h>
#include <stdint.h>

// Problem constants
constexpr int Bd = 2;
constexpr int Td = 2048;
constexpr int Cd = 1024;
constexpr int Hd = 16;
constexpr int Rows = Bd * Td;   // 4096
constexpr int QKVs = 3 * Cd;    // 3072

// ---------------- scratch (device globals) ---------------------------------
__device__ float    g_qkv [Rows * QKVs];
__device__ float    g_P   [(size_t)Bd * Hd * Td * Td];
__device__ float    g_x1  [Rows * Cd];
// packed bf16 hi/lo activations
__device__ uint32_t g_hh  [Rows * Cd / 2],  g_hl  [Rows * Cd / 2];   // LN out
__device__ uint32_t g_ah  [Rows * Cd / 2],  g_al  [Rows * Cd / 2];   // attn out
__device__ uint32_t g_fh  [Rows * 2 * Cd],  g_fl  [Rows * 2 * Cd];   // MLP hidden
// packed bf16 hi/lo weights [K/2][N]
__device__ uint32_t g_wqkv_h[Cd / 2 * QKVs],   g_wqkv_l[Cd / 2 * QKVs];
__device__ uint32_t g_wproj_h[Cd / 2 * Cd],    g_wproj_l[Cd / 2 * Cd];
__device__ uint32_t g_wfc_h [Cd / 2 * 4 * Cd], g_wfc_l [Cd / 2 * 4 * Cd];
__device__ uint32_t g_wfc2_h[2 * Cd * Cd],     g_wfc2_l[2 * Cd * Cd];

// ---------------- helpers ---------------------------------------------------
__device__ __forceinline__ uint32_t packb(float even, float odd) {
    uint32_t r;
    asm("cvt.rn.bf16x2.f32 %0, %1, %2;" : "=r"(r) : "f"(odd), "f"(even));
    return r;
}
__device__ __forceinline__ void splitb(float x, float& hi, float& lo) {
    float h = __bfloat162float(__float2bfloat16_rn(x));
    hi = h; lo = x - h;
}
__device__ __forceinline__ void splitb4(float4 v, float4& hi, float4& lo) {
    splitb(v.x, hi.x, lo.x); splitb(v.y, hi.y, lo.y);
    splitb(v.z, hi.z, lo.z); splitb(v.w, hi.w, lo.w);
}
__device__ __forceinline__ void mma_bf16(float* c, const uint32_t* a, const uint32_t* b) {
    asm volatile(
        "mma.sync.aligned.m16n8k16.row.col.f32.bf16.bf16.f32 "
        "{%0,%1,%2,%3}, {%4,%5,%6,%7}, {%8,%9}, {%0,%1,%2,%3};\n"
        : "+f"(c[0]), "+f"(c[1]), "+f"(c[2]), "+f"(c[3])
        : "r"(a[0]), "r"(a[1]), "r"(a[2]), "r"(a[3]), "r"(b[0]), "r"(b[1]));
}

// ---------------- block reductions ------------------------------------------
__device__ __forceinline__ float block_reduce_sum(float v) {
    __shared__ float sm[32];
    int lane = threadIdx.x & 31, wid = threadIdx.x >> 5;
    #pragma unroll
    for (int o = 16; o; o >>= 1) v += __shfl_down_sync(0xffffffffu, v, o);
    if (lane == 0) sm[wid] = v;
    __syncthreads();
    float r;
    if (wid == 0) {
        float t = (lane < 8) ? sm[lane] : 0.0f;
        #pragma unroll
        for (int o = 4; o; o >>= 1) t += __shfl_down_sync(0xffu, t, o);
        if (lane == 0) sm[0] = t;
    }
    __syncthreads();
    r = sm[0];
    __syncthreads();
    return r;
}
__device__ __forceinline__ float block_reduce_max(float v) {
    __shared__ float sm[32];
    int lane = threadIdx.x & 31, wid = threadIdx.x >> 5;
    #pragma unroll
    for (int o = 16; o; o >>= 1) v = fmaxf(v, __shfl_down_sync(0xffffffffu, v, o));
    if (lane == 0) sm[wid] = v;
    __syncthreads();
    float r;
    if (wid == 0) {
        float t = (lane < 8) ? sm[lane] : -INFINITY;
        #pragma unroll
        for (int o = 4; o; o >>= 1) t = fmaxf(t, __shfl_down_sync(0xffu, t, o));
        if (lane == 0) sm[0] = t;
    }
    __syncthreads();
    r = sm[0];
    __syncthreads();
    return r;
}

// ---------------- weight split: [K][N] fp32 -> [K/2][N] u32 hi/lo -----------
__global__ __launch_bounds__(256) void prep_w(const float* __restrict__ W,
                                              uint32_t* __restrict__ Wh,
                                              uint32_t* __restrict__ Wl,
                                              int Kp, int N) {
    size_t id = (size_t)blockIdx.x * 256 + threadIdx.x;
    size_t total = (size_t)Kp * (N >> 2);
    if (id >= total) return;
    int n4 = (int)(id % (N >> 2)) * 4;
    size_t kp = id / (N >> 2);
    float4 v0 = *(const float4*)(W + (2 * kp) * N + n4);
    float4 v1 = *(const float4*)(W + (2 * kp + 1) * N + n4);
    float4 h0, l0, h1, l1;
    splitb4(v0, h0, l0); splitb4(v1, h1, l1);
    *(uint4*)(Wh + kp * N + n4) = make_uint4(packb(h0.x, h1.x), packb(h0.y, h1.y),
                                             packb(h0.z, h1.z), packb(h0.w, h1.w));
    *(uint4*)(Wl + kp * N + n4) = make_uint4(packb(l0.x, l1.x), packb(l0.y, l1.y),
                                             packb(l0.z, l1.z), packb(l0.w, l1.w));
}

// ---------------- LayerNorm with split packed output ------------------------
__global__ __launch_bounds__(256) void ln_split_k(const float* __restrict__ x,
                                                  const float* __restrict__ w,
                                                  const float* __restrict__ b,
                                                  uint32_t* __restrict__ yh,
                                                  uint32_t* __restrict__ yl) {
    const int row = blockIdx.x;
    const float* xr = x + (size_t)row * Cd;
    float4 v = *(const float4*)(xr + threadIdx.x * 4);
    float s  = v.x + v.y + v.z + v.w;
    float sq = v.x * v.x + v.y * v.y + v.z * v.z + v.w * v.w;
    float sum  = block_reduce_sum(s);
    float sumq = block_reduce_sum(sq);
    float mean = sum * (1.0f / Cd);
    float var  = sumq * (1.0f / Cd) - mean * mean;
    float rstd = rsqrtf(var + 1e-5f);
    int c = threadIdx.x * 4;
    float4 wv = *(const float4*)(w + c);
    float4 bv = *(const float4*)(b + c);
    float4 o;
    o.x = (v.x - mean) * rstd * wv.x + bv.x;
    o.y = (v.y - mean) * rstd * wv.y + bv.y;
    o.z = (v.z - mean) * rstd * wv.z + bv.z;
    o.w = (v.w - mean) * rstd * wv.w + bv.w;
    float4 h, l; splitb4(o, h, l);
    *(uint2*)(yh + (size_t)row * (Cd / 2) + (c >> 1)) = make_uint2(packb(h.x, h.y), packb(h.z, h.w));
    *(uint2*)(yl + (size_t)row * (Cd / 2) + (c >> 1)) = make_uint2(packb(l.x, l.y), packb(l.z, l.w));
}

// ---------------- 3xBF16 GEMM on pre-split inputs, double buffered ----------
// A: [M][Kp] u32 hi/lo (k-pairs), B: [Kp][N] u32 hi/lo. Kp = K/2.
// EPI: 0 bias, 1 bias+res, 2 gelu(bias+.). OUTS: 1 -> write packed hi/lo.
template <int EPI, int OUTS>
__global__ __launch_bounds__(256) void tgemm_sp(int M, int N, int Kp,
                                                const uint32_t* __restrict__ Ahg,
                                                const uint32_t* __restrict__ Alg,
                                                const uint32_t* __restrict__ Bhg,
                                                const uint32_t* __restrict__ Blg,
                                                const float* __restrict__ bias,
                                                const float* __restrict__ res,
                                                float* __restrict__ C,
                                                uint32_t* __restrict__ Chi,
                                                uint32_t* __restrict__ Clo) {
    __shared__ uint32_t Ah[2][128][12], Al[2][128][12];   // 8 data + 4 pad
    __shared__ uint32_t Bh[2][8][136],  Bl[2][8][136];    // 128 data + 8 pad
    const int tid = threadIdx.x, lane = tid & 31, warp = tid >> 5;
    const int warpM = warp >> 2, warpN = warp & 3;        // 2 x 4 warps
    const size_t bM = (size_t)blockIdx.y * 128, bN = (size_t)blockIdx.x * 128;

    const int aRow = tid >> 1, aK = (tid & 1) * 4;        // A: 128 rows x 8 kk
    const int bK = tid >> 5, bN4 = (tid & 31) * 4;        // B: 8 kk x 128 n

    const int nch = Kp >> 3;
    uint4 rah, ral, rbh, rbl;
    // prologue load stage 0
    rah = *(const uint4*)(Ahg + (bM + aRow) * Kp + aK);
    ral = *(const uint4*)(Alg + (bM + aRow) * Kp + aK);
    rbh = *(const uint4*)(Bhg + (size_t)bK * N + bN + bN4);
    rbl = *(const uint4*)(Blg + (size_t)bK * N + bN + bN4);
    *(uint4*)&Ah[0][aRow][aK] = rah; *(uint4*)&Al[0][aRow][aK] = ral;
    *(uint4*)&Bh[0][bK][bN4]  = rbh; *(uint4*)&Bl[0][bK][bN4]  = rbl;
    __syncthreads();

    float acc[4][4][4] = {};
    for (int c = 0; c < nch; c++) {
        const int s = c & 1;
        if (c + 1 < nch) {
            rah = *(const uint4*)(Ahg + (bM + aRow) * Kp + (c + 1) * 8 + aK);
            ral = *(const uint4*)(Alg + (bM + aRow) * Kp + (c + 1) * 8 + aK);
            rbh = *(const uint4*)(Bhg + (size_t)((c + 1) * 8 + bK) * N + bN + bN4);
            rbl = *(const uint4*)(Blg + (size_t)((c + 1) * 8 + bK) * N + bN + bN4);
        }
        const int kk = lane & 3, fr = lane >> 2;
        uint32_t a_h[4][4], a_l[4][4], b_h[4][2], b_l[4][2];
        #pragma unroll
        for (int mt = 0; mt < 4; mt++) {
            int r = warpM * 64 + mt * 16 + fr;
            a_h[mt][0] = Ah[s][r][kk];     a_h[mt][1] = Ah[s][r + 8][kk];
            a_h[mt][2] = Ah[s][r][kk + 4]; a_h[mt][3] = Ah[s][r + 8][kk + 4];
            a_l[mt][0] = Al[s][r][kk];     a_l[mt][1] = Al[s][r + 8][kk];
            a_l[mt][2] = Al[s][r][kk + 4]; a_l[mt][3] = Al[s][r + 8][kk + 4];
        }
        #pragma unroll
        for (int nt = 0; nt < 4; nt++) {
            int n = warpN * 32 + nt * 8 + fr;
            b_h[nt][0] = Bh[s][kk][n]; b_h[nt][1] = Bh[s][kk + 4][n];
            b_l[nt][0] = Bl[s][kk][n]; b_l[nt][1] = Bl[s][kk + 4][n];
        }
        #pragma unroll
        for (int mt = 0; mt < 4; mt++)
            #pragma unroll
            for (int nt = 0; nt < 4; nt++) {
                mma_bf16(acc[mt][nt], a_l[mt], b_h[nt]);
                mma_bf16(acc[mt][nt], a_h[mt], b_l[nt]);
                mma_bf16(acc[mt][nt], a_h[mt], b_h[nt]);
            }
        if (c + 1 < nch) {
            *(uint4*)&Ah[s ^ 1][aRow][aK] = rah; *(uint4*)&Al[s ^ 1][aRow][aK] = ral;
            *(uint4*)&Bh[s ^ 1][bK][bN4]  = rbh; *(uint4*)&Bl[s ^ 1][bK][bN4]  = rbl;
        }
        __syncthreads();
    }
    // epilogue
    #pragma unroll
    for (int mt = 0; mt < 4; mt++) {
        #pragma unroll
        for (int nt = 0; nt < 4; nt++) {
            size_t r0 = bM + warpM * 64 + mt * 16 + (lane >> 2);
            size_t cb = bN + warpN * 32 + nt * 8 + (lane & 3) * 2;
            float b0 = bias[cb], b1 = bias[cb + 1];
            #pragma unroll
            for (int half = 0; half < 2; half++) {
                size_t r = r0 + half * 8;
                float v0 = acc[mt][nt][half * 2 + 0] + b0;
                float v1 = acc[mt][nt][half * 2 + 1] + b1;
                if (EPI == 1) {
                    const float* rp = res + r * N + cb;
                    v0 += rp[0]; v1 += rp[1];
                }
                if (EPI == 2) {
                    v0 = 0.5f * v0 * (1.0f + erff(v0 * 0.70710678118654752f));
                    v1 = 0.5f * v1 * (1.0f + erff(v1 * 0.70710678118654752f));
                }
                if (OUTS) {
                    float h0, l0, h1, l1;
                    splitb(v0, h0, l0); splitb(v1, h1, l1);
                    Chi[r * (N / 2) + (cb >> 1)] = packb(h0, h1);
                    Clo[r * (N / 2) + (cb >> 1)] = packb(l0, l1);
                } else {
                    *(float2*)(C + r * N + cb) = make_float2(v0, v1);
                }
            }
        }
    }
}

// ---------------- scores: S = Q K^T * scale (lower blocks), 3xBF16 ----------
__global__ __launch_bounds__(128) void scores_tc(const float* __restrict__ qkv,
                                                 float* __restrict__ P) {
    const int bh = blockIdx.z;
    const int b = bh >> 4, h = bh & 15;
    const int t0 = blockIdx.y * 64, s0 = blockIdx.x * 64;
    if (s0 > t0) return;
    __shared__ uint32_t Qh[64][36], Ql[64][36];
    __shared__ uint32_t Kh[64][36], Kl[64][36];
    const int tid = threadIdx.x, lane = tid & 31, warp = tid >> 5;
    const int warpM = warp >> 1, warpN = warp & 1;
    const float* qb = qkv + (size_t)(b * Td + t0) * QKVs + h * 64;
    const float* kb = qkv + (size_t)(b * Td + s0) * QKVs + Cd + h * 64;
    #pragma unroll
    for (int i = 0; i < 8; i++) {
        int idx = tid + i * 128;
        int r = idx >> 4, c4 = (idx & 15) * 4;
        float4 hi, lo;
        splitb4(*(const float4*)(qb + (size_t)r * QKVs + c4), hi, lo);
        *(uint2*)&Qh[r][c4 >> 1] = make_uint2(packb(hi.x, hi.y), packb(hi.z, hi.w));
        *(uint2*)&Ql[r][c4 >> 1] = make_uint2(packb(lo.x, lo.y), packb(lo.z, lo.w));
        splitb4(*(const float4*)(kb + (size_t)r * QKVs + c4), hi, lo);
        *(uint2*)&Kh[r][c4 >> 1] = make_uint2(packb(hi.x, hi.y), packb(hi.z, hi.w));
        *(uint2*)&Kl[r][c4 >> 1] = make_uint2(packb(lo.x, lo.y), packb(lo.z, lo.w));
    }
    __syncthreads();
    float acc[2][4][4] = {};
    #pragma unroll
    for (int ks = 0; ks < 4; ks++) {
        const int kb0 = ks * 8 + (lane & 3), fr = lane >> 2;
        uint32_t a_h[2][4], a_l[2][4], b_h[4][2], b_l[4][2];
        #pragma unroll
        for (int mt = 0; mt < 2; mt++) {
            int r = warpM * 32 + mt * 16 + fr;
            a_h[mt][0] = Qh[r][kb0];     a_h[mt][1] = Qh[r + 8][kb0];
            a_h[mt][2] = Qh[r][kb0 + 4]; a_h[mt][3] = Qh[r + 8][kb0 + 4];
            a_l[mt][0] = Ql[r][kb0];     a_l[mt][1] = Ql[r + 8][kb0];
            a_l[mt][2] = Ql[r][kb0 + 4]; a_l[mt][3] = Ql[r + 8][kb0 + 4];
        }
        #pragma unroll
        for (int nt = 0; nt < 4; nt++) {
            int n = warpN * 32 + nt * 8 + fr;
            b_h[nt][0] = Kh[n][kb0]; b_h[nt][1] = Kh[n][kb0 + 4];
            b_l[nt][0] = Kl[n][kb0]; b_l[nt][1] = Kl[n][kb0 + 4];
        }
        #pragma unroll
        for (int mt = 0; mt < 2; mt++)
            #pragma unroll
            for (int nt = 0; nt < 4; nt++) {
                mma_bf16(acc[mt][nt], a_l[mt], b_h[nt]);
                mma_bf16(acc[mt][nt], a_h[mt], b_l[nt]);
                mma_bf16(acc[mt][nt], a_h[mt], b_h[nt]);
            }
    }
    const float scale = 0.125f;
    #pragma unroll
    for (int mt = 0; mt < 2; mt++) {
        #pragma unroll
        for (int nt = 0; nt < 4; nt++) {
            int r0 = t0 + warpM * 32 + mt * 16 + (lane >> 2);
            int cb = s0 + warpN * 32 + nt * 8 + (lane & 3) * 2;
            #pragma unroll
            for (int half = 0; half < 2; half++) {
                int r = r0 + half * 8;
                float2 o = make_float2(acc[mt][nt][half * 2] * scale,
                                       acc[mt][nt][half * 2 + 1] * scale);
                *(float2*)(P + ((size_t)bh * Td + r) * Td + cb) = o;
            }
        }
    }
}

// ---------------- causal softmax per row (float4, smem buffer) --------------
__global__ __launch_bounds__(256) void softmax_k(float* __restrict__ P) {
    __shared__ float buf[Td];
    const size_t r = blockIdx.x;
    const int t = (int)(r & (Td - 1));
    float* row = P + r * Td;
    const int n = t + 1, n4 = n >> 2, tail = n4 * 4;
    float4* row4 = (float4*)row;
    float4* buf4 = (float4*)buf;
    float m = -INFINITY;
    for (int i = threadIdx.x; i < n4; i += 256) {
        float4 v = row4[i];
        buf4[i] = v;
        m = fmaxf(m, fmaxf(fmaxf(v.x, v.y), fmaxf(v.z, v.w)));
    }
    {
        int i = tail + threadIdx.x;
        if (i < n) { float v = row[i]; buf[i] = v; m = fmaxf(m, v); }
    }
    m = block_reduce_max(m);
    float s = 0.0f;
    for (int i = threadIdx.x; i < n4; i += 256) {
        float4 v = buf4[i];
        v.x = __expf(v.x - m); v.y = __expf(v.y - m);
        v.z = __expf(v.z - m); v.w = __expf(v.w - m);
        buf4[i] = v;
        s += v.x + v.y + v.z + v.w;
    }
    {
        int i = tail + threadIdx.x;
        if (i < n) { float e = __expf(buf[i] - m); buf[i] = e; s += e; }
    }
    s = block_reduce_sum(s);
    const float inv = 1.0f / s;
    for (int i = threadIdx.x; i < n4; i += 256) {
        float4 v = buf4[i];
        v.x *= inv; v.y *= inv; v.z *= inv; v.w *= inv;
        row4[i] = v;
    }
    {
        int i = tail + threadIdx.x;
        if (i < n) row[i] = buf[i] * inv;
    }
    const int fillEnd = ((t >> 6) << 6) + 64;
    for (int i = n + (int)threadIdx.x; i < fillEnd; i += 256) row[i] = 0.0f;
}

// ---------------- attn_mean --------------------------------------------------
__global__ __launch_bounds__(256) void attnmean_k(const float* __restrict__ P,
                                                  float* __restrict__ out) {
    const size_t i4 = (size_t)blockIdx.x * 256 + threadIdx.x;
    const int scol = (int)(i4 & (Td / 4 - 1)) * 4;
    const int t = (int)((i4 >> 9) & (Td - 1));
    const size_t off = (size_t)Hd * Td * Td;
    float4 o;
    if (scol > t) {
        o = make_float4(0.f, 0.f, 0.f, 0.f);
    } else {
        float4 a = *(const float4*)(P + i4 * 4);
        float4 b = *(const float4*)(P + i4 * 4 + off);
        o.x = 0.5f * (a.x + b.x); o.y = 0.5f * (a.y + b.y);
        o.z = 0.5f * (a.z + b.z); o.w = 0.5f * (a.w + b.w);
    }
    *(float4*)(out + i4 * 4) = o;
}

// ---------------- attn_out = P @ V (triangular), 3xBF16, split output -------
__global__ __launch_bounds__(128) void pv_tc(const float* __restrict__ P,
                                             const float* __restrict__ qkv,
                                             uint32_t* __restrict__ outh,
                                             uint32_t* __restrict__ outl) {
    const int bh = blockIdx.y;
    const int b = bh >> 4, h = bh & 15;
    const int t0 = blockIdx.x * 64;
    __shared__ uint32_t Ph[64][36], Pl[64][36];
    __shared__ uint32_t Vh[32][72], Vl[32][72];
    const int tid = threadIdx.x, lane = tid & 31, warp = tid >> 5;
    const int warpM = warp >> 1, warpN = warp & 1;
    float acc[2][4][4] = {};
    for (int s0 = 0; s0 <= t0; s0 += 64) {
        #pragma unroll
        for (int i = 0; i < 8; i++) {
            int idx = tid + i * 128;
            int r = idx >> 4, c4 = (idx & 15) * 4;
            float4 hi, lo;
            splitb4(*(const float4*)(P + ((size_t)bh * Td + t0 + r) * Td + s0 + c4), hi, lo);
            *(uint2*)&Ph[r][c4 >> 1] = make_uint2(packb(hi.x, hi.y), packb(hi.z, hi.w));
            *(uint2*)&Pl[r][c4 >> 1] = make_uint2(packb(lo.x, lo.y), packb(lo.z, lo.w));
        }
        #pragma unroll
        for (int i = 0; i < 4; i++) {
            int idx = tid + i * 128;
            int kkr = idx >> 4, n4 = (idx & 15) * 4;
            const float* vb = qkv + (size_t)(b * Td + s0) * QKVs + 2 * Cd + h * 64;
            float4 hA, lA, hB, lB;
            splitb4(*(const float4*)(vb + (size_t)(2 * kkr) * QKVs + n4), hA, lA);
            splitb4(*(const float4*)(vb + (size_t)(2 * kkr + 1) * QKVs + n4), hB, lB);
            *(uint4*)&Vh[kkr][n4] = make_uint4(packb(hA.x, hB.x), packb(hA.y, hB.y),
                                               packb(hA.z, hB.z), packb(hA.w, hB.w));
            *(uint4*)&Vl[kkr][n4] = make_uint4(packb(lA.x, lB.x), packb(lA.y, lB.y),
                                               packb(lA.z, lB.z), packb(lA.w, lB.w));
        }
        __syncthreads();
        #pragma unroll
        for (int ks = 0; ks < 4; ks++) {
            const int kb0 = ks * 8 + (lane & 3), fr = lane >> 2;
            uint32_t a_h[2][4], a_l[2][4], b_h[4][2], b_l[4][2];
            #pragma unroll
            for (int mt = 0; mt < 2; mt++) {
                int r = warpM * 32 + mt * 16 + fr;
                a_h[mt][0] = Ph[r][kb0];     a_h[mt][1] = Ph[r + 8][kb0];
                a_h[mt][2] = Ph[r][kb0 + 4]; a_h[mt][3] = Ph[r + 8][kb0 + 4];
                a_l[mt][0] = Pl[r][kb0];     a_l[mt][1] = Pl[r + 8][kb0];
                a_l[mt][2] = Pl[r][kb0 + 4]; a_l[mt][3] = Pl[r + 8][kb0 + 4];
            }
            #pragma unroll
            for (int nt = 0; nt < 4; nt++) {
                int n = warpN * 32 + nt * 8 + fr;
                b_h[nt][0] = Vh[kb0][n]; b_h[nt][1] = Vh[kb0 + 4][n];
                b_l[nt][0] = Vl[kb0][n]; b_l[nt][1] = Vl[kb0 + 4][n];
            }
            #pragma unroll
            for (int mt = 0; mt < 2; mt++)
                #pragma unroll
                for (int nt = 0; nt < 4; nt++) {
                    mma_bf16(acc[mt][nt], a_l[mt], b_h[nt]);
                    mma_bf16(acc[mt][nt], a_h[mt], b_l[nt]);
                    mma_bf16(acc[mt][nt], a_h[mt], b_h[nt]);
                }
        }
        __syncthreads();
    }
    #pragma unroll
    for (int mt = 0; mt < 2; mt++) {
        #pragma unroll
        for (int nt = 0; nt < 4; nt++) {
            int r0 = t0 + warpM * 32 + mt * 16 + (lane >> 2);
            int cb = warpN * 32 + nt * 8 + (lane & 3) * 2;
            #pragma unroll
            for (int half = 0; half < 2; half++) {
                int r = r0 + half * 8;
                float v0 = acc[mt][nt][half * 2], v1 = acc[mt][nt][half * 2 + 1];
                float h0, l0, h1, l1;
                splitb(v0, h0, l0); splitb(v1, h1, l1);
                size_t o = (size_t)(b * Td + r) * (Cd / 2) + ((h * 64 + cb) >> 1);
                outh[o] = packb(h0, h1);
                outl[o] = packb(l0, l1);
            }
        }
    }
}

// ---------------- launch -----------------------------------------------------
extern "C" void kernel_launch(void* const* d_in, const int* in_sizes, int n_in,
                              void* d_out, int out_size) {
    const float* x      = (const float*)d_in[0];
    const float* ln1_w  = (const float*)d_in[1];
    const float* ln1_b  = (const float*)d_in[2];
    const float* w_qkv  = (const float*)d_in[3];
    const float* b_qkv  = (const float*)d_in[4];
    const float* w_proj = (const float*)d_in[5];
    const float* b_proj = (const float*)d_in[6];
    const float* ln2_w  = (const float*)d_in[7];
    const float* ln2_b  = (const float*)d_in[8];
    const float* w_fc   = (const float*)d_in[9];
    const float* b_fc   = (const float*)d_in[10];
    const float* w_fc2  = (const float*)d_in[11];
    const float* b_fc2  = (const float*)d_in[12];

    float* out_x    = (float*)d_out;
    float* out_attn = (float*)d_out + (size_t)Rows * Cd;

    float *gqkv, *gP, *gx1;
    uint32_t *ghh, *ghl, *gah, *gal, *gfh, *gfl;
    uint32_t *wqh, *wql, *wph, *wpl, *wfh, *wfl, *w2h, *w2l;
    cudaGetSymbolAddress((void**)&gqkv, g_qkv);
    cudaGetSymbolAddress((void**)&gP,   g_P);
    cudaGetSymbolAddress((void**)&gx1,  g_x1);
    cudaGetSymbolAddress((void**)&ghh,  g_hh);  cudaGetSymbolAddress((void**)&ghl, g_hl);
    cudaGetSymbolAddress((void**)&gah,  g_ah);  cudaGetSymbolAddress((void**)&gal, g_al);
    cudaGetSymbolAddress((void**)&gfh,  g_fh);  cudaGetSymbolAddress((void**)&gfl, g_fl);
    cudaGetSymbolAddress((void**)&wqh,  g_wqkv_h);  cudaGetSymbolAddress((void**)&wql, g_wqkv_l);
    cudaGetSymbolAddress((void**)&wph,  g_wproj_h); cudaGetSymbolAddress((void**)&wpl, g_wproj_l);
    cudaGetSymbolAddress((void**)&wfh,  g_wfc_h);   cudaGetSymbolAddress((void**)&wfl, g_wfc_l);
    cudaGetSymbolAddress((void**)&w2h,  g_wfc2_h);  cudaGetSymbolAddress((void**)&w2l, g_wfc2_l);

    // weight splits (every call; deterministic, ~15us total)
    prep_w<<<(512 * (QKVs / 4) + 255) / 256, 256>>>(w_qkv, wqh, wql, 512, QKVs);
    prep_w<<<(512 * (Cd / 4) + 255) / 256, 256>>>(w_proj, wph, wpl, 512, Cd);
    prep_w<<<(512 * Cd + 255) / 256, 256>>>(w_fc, wfh, wfl, 512, 4 * Cd);
    prep_w<<<(2048 * (Cd / 4) + 255) / 256, 256>>>(w_fc2, w2h, w2l, 2048, Cd);

    ln_split_k<<<Rows, 256>>>(x, ln1_w, ln1_b, ghh, ghl);
    tgemm_sp<0, 0><<<dim3(QKVs / 128, Rows / 128), 256>>>(Rows, QKVs, Cd / 2,
        ghh, ghl, wqh, wql, b_qkv, nullptr, gqkv, nullptr, nullptr);
    scores_tc<<<dim3(Td / 64, Td / 64, Bd * Hd), 128>>>(gqkv, gP);
    softmax_k<<<Bd * Hd * Td, 256>>>(gP);
    attnmean_k<<<(unsigned)((size_t)Hd * Td * Td / 4 / 256), 256>>>(gP, out_attn);
    pv_tc<<<dim3(Td / 64, Bd * Hd), 128>>>(gP, gqkv, gah, gal);
    tgemm_sp<1, 0><<<dim3(Cd / 128, Rows / 128), 256>>>(Rows, Cd, Cd / 2,
        gah, gal, wph, wpl, b_proj, x, gx1, nullptr, nullptr);
    ln_split_k<<<Rows, 256>>>(gx1, ln2_w, ln2_b, ghh, ghl);
    tgemm_sp<2, 1><<<dim3(4 * Cd / 128, Rows / 128), 256>>>(Rows, 4 * Cd, Cd / 2,
        ghh, ghl, wfh, wfl, b_fc, nullptr, nullptr, gfh, gfl);
    tgemm_sp<1, 0><<<dim3(Cd / 128, Rows / 128), 256>>>(Rows, Cd, 2 * Cd,
        gfh, gfl, w2h, w2l, b_fc2, gx1, out_x, nullptr, nullptr);
}